// round 1
// baseline (speedup 1.0000x reference)
#include <cuda_runtime.h>
#include <stdint.h>

#define D 128
#define K 16
#define TPB 256
#define ROWS_TILE 512          // rows per block
#define CH 32                  // columns per smem stage
#define NCH (D / CH)           // 4 stages
#define XS_STRIDE 17           // float2 per row (16 data + 1 pad) -> conflict-free LDS.64

// Precomputed A in (cp, k) pair-major layout: gAp[(cp*K + k)] is float2 = (A[k][2cp], A[k][2cp+1])
__device__ __align__(16) float gAp[(D / 2) * K * 2];   // 2048 floats
__device__ float gC[K];

// ---------------- packed f32x2 helpers ----------------
__device__ __forceinline__ void ffma2(unsigned long long& c, unsigned long long a, unsigned long long b) {
    asm("fma.rn.f32x2 %0, %1, %2, %0;" : "+l"(c) : "l"(a), "l"(b));
}
__device__ __forceinline__ void unpack2(float& lo, float& hi, unsigned long long v) {
    asm("mov.b64 {%0, %1}, %2;" : "=f"(lo), "=f"(hi) : "l"(v));
}

// ---------------- prep kernel: A = V[:, :D] + W @ x2 ; c = V[:, D:] @ x2 + b ----------------
__global__ void ntn_prep(const float* __restrict__ x2,
                         const float* __restrict__ V,
                         const float* __restrict__ W,
                         const float* __restrict__ b) {
    __shared__ float x2s[D];
    __shared__ float red[D];
    const int k = blockIdx.x;
    const int d = threadIdx.x;

    x2s[d] = x2[d];
    __syncthreads();

    // wx2[k][d] = sum_e W[k][d][e] * x2[e]
    const float* wrow = W + ((size_t)k * D + d) * D;
    float dot = 0.f;
#pragma unroll 8
    for (int e = 0; e < D; e++) dot = fmaf(wrow[e], x2s[e], dot);

    const float a = V[(size_t)k * 2 * D + d] + dot;
    // store in (cp, k, half) layout
    const int cp = d >> 1, half = d & 1;
    gAp[(cp * K + k) * 2 + half] = a;

    // c[k] = sum_e V[k][D+e] * x2[e] + b[k]
    red[d] = V[(size_t)k * 2 * D + D + d] * x2s[d];
    __syncthreads();
#pragma unroll
    for (int s = 64; s > 0; s >>= 1) {
        if (d < s) red[d] += red[d + s];
        __syncthreads();
    }
    if (d == 0) gC[k] = red[0] + b[k];
}

// ---------------- main kernel ----------------
__global__ __launch_bounds__(TPB, 2)
void ntn_main(const float* __restrict__ x1,
              const float* __restrict__ U,
              float* __restrict__ out, int n) {
    extern __shared__ __align__(16) char smem_raw[];
    // layout: sA (1024 ull = 8KB) | sC (16 f) | sU (16 f) | pad | xs (512 x 17 float2)
    unsigned long long* sA = (unsigned long long*)smem_raw;            // [ (D/2) * K/2 ull2 ] as ull[1024]
    float* sC = (float*)(smem_raw + 8192);
    float* sU = sC + K;
    float2* xs = (float2*)(smem_raw + 8192 + 256);                     // [ROWS_TILE][XS_STRIDE]

    const int tid = threadIdx.x;

    // Load A (1024 x 8B), c, U into smem
    {
        const unsigned long long* gAu = (const unsigned long long*)gAp;
#pragma unroll
        for (int i = 0; i < 4; i++) sA[tid + i * TPB] = gAu[tid + i * TPB];
        if (tid < K) { sC[tid] = gC[tid]; sU[tid] = U[tid]; }
    }

    const int row0 = blockIdx.x * ROWS_TILE;
    const int ra = row0 + tid;          // this thread's row A
    const int rb = ra + TPB;            // this thread's row B

    unsigned long long acc0[K], acc1[K];
#pragma unroll
    for (int k = 0; k < K; k++) { acc0[k] = 0ull; acc1[k] = 0ull; }

    for (int ch = 0; ch < NCH; ch++) {
        __syncthreads();
        // cooperative coalesced load: 512 rows x 32 cols (8 float4 per row)
#pragma unroll
        for (int it = 0; it < 16; it++) {
            const int idx = it * TPB + tid;
            const int r = idx >> 3;           // 0..511
            const int c4 = idx & 7;           // 0..7 float4 within the 32-col chunk
            const int grow = row0 + r;
            float4 v = make_float4(0.f, 0.f, 0.f, 0.f);
            if (grow < n)
                v = *(const float4*)(x1 + (size_t)grow * D + ch * CH + c4 * 4);
            // two STS.64 (stride 17 float2 keeps loads conflict-free; float4 store would be misaligned)
            float2* p = xs + (size_t)r * XS_STRIDE + c4 * 2;
            p[0] = make_float2(v.x, v.y);
            p[1] = make_float2(v.z, v.w);
        }
        __syncthreads();

        const unsigned long long* xr0 = (const unsigned long long*)(xs + (size_t)tid * XS_STRIDE);
        const unsigned long long* xr1 = (const unsigned long long*)(xs + (size_t)(tid + TPB) * XS_STRIDE);

#pragma unroll
        for (int cpl = 0; cpl < CH / 2; cpl++) {
            const unsigned long long xa = xr0[cpl];
            const unsigned long long xb = xr1[cpl];
            const int cp = ch * (CH / 2) + cpl;
            const ulonglong2* Ab = (const ulonglong2*)(sA + cp * K);
#pragma unroll
            for (int j = 0; j < K / 2; j++) {
                const ulonglong2 a2 = Ab[j];     // A pairs for k=2j, 2j+1 (broadcast LDS.128)
                ffma2(acc0[2 * j],     xa, a2.x);
                ffma2(acc0[2 * j + 1], xa, a2.y);
                ffma2(acc1[2 * j],     xb, a2.x);
                ffma2(acc1[2 * j + 1], xb, a2.y);
            }
        }
    }

    // epilogue: out[r] = sum_k relu(dot_k + c[k]) * U[k]
    float res0 = 0.f, res1 = 0.f;
#pragma unroll
    for (int k = 0; k < K; k++) {
        float lo, hi;
        unpack2(lo, hi, acc0[k]);
        float s0 = lo + hi + sC[k];
        res0 = fmaf(fmaxf(s0, 0.f), sU[k], res0);
        unpack2(lo, hi, acc1[k]);
        float s1 = lo + hi + sC[k];
        res1 = fmaf(fmaxf(s1, 0.f), sU[k], res1);
    }
    if (ra < n) out[ra] = res0;
    if (rb < n) out[rb] = res1;
}

// ---------------- launch ----------------
extern "C" void kernel_launch(void* const* d_in, const int* in_sizes, int n_in,
                              void* d_out, int out_size) {
    // Map inputs by size (x1:N*D, x2:D, V:K*2D=4096, W:K*D*D=262144, b:16, U:16 in order)
    const float* x1 = nullptr; const float* x2 = nullptr; const float* V = nullptr;
    const float* W = nullptr;  const float* b = nullptr;  const float* U = nullptr;
    int n16 = 0;
    for (int i = 0; i < n_in; i++) {
        const int s = in_sizes[i];
        const float* p = (const float*)d_in[i];
        if (s == 128) x2 = p;
        else if (s == 4096) V = p;
        else if (s == 262144) W = p;
        else if (s == 16) { if (n16++ == 0) b = p; else U = p; }
        else x1 = p;  // the big one
    }
    int n = 0;
    for (int i = 0; i < n_in; i++) if ((const float*)d_in[i] == x1) n = in_sizes[i] / D;

    float* out = (float*)d_out;

    ntn_prep<<<K, D>>>(x2, V, W, b);

    const int smem_bytes = 8192 + 256 + ROWS_TILE * XS_STRIDE * (int)sizeof(float2);
    cudaFuncSetAttribute(ntn_main, cudaFuncAttributeMaxDynamicSharedMemorySize, smem_bytes);
    const int blocks = (n + ROWS_TILE - 1) / ROWS_TILE;
    ntn_main<<<blocks, TPB, smem_bytes>>>(x1, U, out, n);
}

// round 2
// speedup vs baseline: 2.1365x; 2.1365x over previous
#include <cuda_runtime.h>
#include <stdint.h>

#define D 128
#define K 16
#define TPB 128
#define ROWS_TILE 256          // rows per block (2 per thread)
#define CH 16                  // columns per smem stage
#define NCH (D / CH)           // 8 stages
#define XSTR 9                 // float2 per row (8 data + 1 pad) -> conflict-free LDS.64
#define STAGES 3               // cp.async pipeline depth

// Precomputed A in (cp, k) pair-major layout: gAp[(cp*K + k)] is float2 = (A[k][2cp], A[k][2cp+1])
__device__ __align__(16) float gAp[(D / 2) * K * 2];   // 2048 floats
__device__ float gC[K];

// ---------------- packed f32x2 helpers ----------------
__device__ __forceinline__ void ffma2(unsigned long long& c, unsigned long long a, unsigned long long b) {
    asm("fma.rn.f32x2 %0, %1, %2, %0;" : "+l"(c) : "l"(a), "l"(b));
}
__device__ __forceinline__ void unpack2(float& lo, float& hi, unsigned long long v) {
    asm("mov.b64 {%0, %1}, %2;" : "=f"(lo), "=f"(hi) : "l"(v));
}
__device__ __forceinline__ void cp_async8(uint32_t dst, const void* src, int src_bytes) {
    asm volatile("cp.async.ca.shared.global [%0], [%1], 8, %2;\n"
                 :: "r"(dst), "l"(src), "r"(src_bytes));
}
__device__ __forceinline__ void cp_commit() {
    asm volatile("cp.async.commit_group;\n" ::: "memory");
}
__device__ __forceinline__ void cp_wait1() {
    asm volatile("cp.async.wait_group 1;\n" ::: "memory");
}

// ---------------- prep kernel: A = V[:, :D] + W @ x2 ; c = V[:, D:] @ x2 + b ----------------
__global__ void ntn_prep(const float* __restrict__ x2,
                         const float* __restrict__ V,
                         const float* __restrict__ W,
                         const float* __restrict__ b) {
    __shared__ float x2s[D];
    __shared__ float red[D];
    const int k = blockIdx.x;
    const int d = threadIdx.x;

    x2s[d] = x2[d];
    __syncthreads();

    const float* wrow = W + ((size_t)k * D + d) * D;
    float dot = 0.f;
#pragma unroll 8
    for (int e = 0; e < D; e++) dot = fmaf(wrow[e], x2s[e], dot);

    const float a = V[(size_t)k * 2 * D + d] + dot;
    const int cp = d >> 1, half = d & 1;
    gAp[(cp * K + k) * 2 + half] = a;

    red[d] = V[(size_t)k * 2 * D + D + d] * x2s[d];
    __syncthreads();
#pragma unroll
    for (int s = 64; s > 0; s >>= 1) {
        if (d < s) red[d] += red[d + s];
        __syncthreads();
    }
    if (d == 0) gC[k] = red[0] + b[k];
}

// ---------------- main kernel ----------------
__global__ __launch_bounds__(TPB, 3)
void ntn_main(const float* __restrict__ x1,
              const float* __restrict__ U,
              float* __restrict__ out, int n) {
    extern __shared__ __align__(16) char smem_raw[];
    // layout: sA (1024 ull = 8KB) | sC (16f) | sU (16f) | pad to 8448 | xs[STAGES][256][XSTR] float2
    unsigned long long* sA = (unsigned long long*)smem_raw;
    float* sC = (float*)(smem_raw + 8192);
    float* sU = sC + K;
    float2* xs = (float2*)(smem_raw + 8448);
    const uint32_t xs_u32 = (uint32_t)__cvta_generic_to_shared(xs);

    const int tid = threadIdx.x;

    // Load A (1024 x 8B), c, U into smem (covered by the first pipeline barrier)
    {
        const unsigned long long* gAu = (const unsigned long long*)gAp;
#pragma unroll
        for (int i = 0; i < 8; i++) sA[tid + i * TPB] = gAu[tid + i * TPB];
        if (tid < K) { sC[tid] = gC[tid]; sU[tid] = U[tid]; }
    }

    const int row0 = blockIdx.x * ROWS_TILE;

    // cp.async issue for one chunk into one stage buffer.
    // Per thread: 16 x 8B. idx = it*TPB + tid; r = idx>>3; c = idx&7 (float2 within chunk row)
    auto issue_chunk = [&](int ch, int buf) {
        const uint32_t base = xs_u32 + (uint32_t)buf * (ROWS_TILE * XSTR * 8);
#pragma unroll
        for (int it = 0; it < 16; it++) {
            const int idx = it * TPB + tid;
            const int r = idx >> 3;
            const int c = idx & 7;
            const int grow = row0 + r;
            const int ok = (grow < n);
            const float* src = x1 + (size_t)(ok ? grow : 0) * D + ch * CH + c * 2;
            cp_async8(base + (uint32_t)(r * XSTR + c) * 8u, src, ok ? 8 : 0);
        }
    };

    unsigned long long acc0[K], acc1[K];
#pragma unroll
    for (int k = 0; k < K; k++) { acc0[k] = 0ull; acc1[k] = 0ull; }

    // prologue: stage first STAGES-1 chunks
#pragma unroll
    for (int s = 0; s < STAGES - 1; s++) { issue_chunk(s, s); cp_commit(); }

    for (int ch = 0; ch < NCH; ch++) {
        // keep the pipe full: issue chunk ch+STAGES-1
        if (ch + STAGES - 1 < NCH) issue_chunk(ch + STAGES - 1, (ch + STAGES - 1) % STAGES);
        cp_commit();                 // commit every iteration (possibly empty) to keep group count aligned
        cp_wait1();                  // <=1 group pending => chunk ch landed
        __syncthreads();

        const int buf = ch % STAGES;
        const unsigned long long* xr0 = (const unsigned long long*)
            (xs + (size_t)buf * ROWS_TILE * XSTR + (size_t)tid * XSTR);
        const unsigned long long* xr1 = xr0 + (size_t)TPB * XSTR;

#pragma unroll
        for (int cpl = 0; cpl < CH / 2; cpl++) {
            const unsigned long long xa = xr0[cpl];
            const unsigned long long xb = xr1[cpl];
            const int cp = ch * (CH / 2) + cpl;
            const ulonglong2* Ab = (const ulonglong2*)(sA + cp * K);
#pragma unroll
            for (int j = 0; j < K / 2; j++) {
                const ulonglong2 a2 = Ab[j];   // broadcast LDS.128: A pairs for k=2j, 2j+1
                ffma2(acc0[2 * j],     xa, a2.x);
                ffma2(acc0[2 * j + 1], xa, a2.y);
                ffma2(acc1[2 * j],     xb, a2.x);
                ffma2(acc1[2 * j + 1], xb, a2.y);
            }
        }
        __syncthreads();   // protect buf before chunk ch+STAGES overwrites it
    }

    // epilogue: out[r] = sum_k relu(dot_k + c[k]) * U[k]
    float res0 = 0.f, res1 = 0.f;
#pragma unroll
    for (int k = 0; k < K; k++) {
        float lo, hi;
        unpack2(lo, hi, acc0[k]);
        float s0 = lo + hi + sC[k];
        res0 = fmaf(fmaxf(s0, 0.f), sU[k], res0);
        unpack2(lo, hi, acc1[k]);
        float s1 = lo + hi + sC[k];
        res1 = fmaf(fmaxf(s1, 0.f), sU[k], res1);
    }
    const int ra = row0 + tid;
    const int rb = ra + TPB;
    if (ra < n) out[ra] = res0;
    if (rb < n) out[rb] = res1;
}

// ---------------- launch ----------------
extern "C" void kernel_launch(void* const* d_in, const int* in_sizes, int n_in,
                              void* d_out, int out_size) {
    const float* x1 = nullptr; const float* x2 = nullptr; const float* V = nullptr;
    const float* W = nullptr;  const float* b = nullptr;  const float* U = nullptr;
    int n16 = 0;
    for (int i = 0; i < n_in; i++) {
        const int s = in_sizes[i];
        const float* p = (const float*)d_in[i];
        if (s == 128) x2 = p;
        else if (s == 4096) V = p;
        else if (s == 262144) W = p;
        else if (s == 16) { if (n16++ == 0) b = p; else U = p; }
        else x1 = p;
    }
    int n = 0;
    for (int i = 0; i < n_in; i++) if ((const float*)d_in[i] == x1) n = in_sizes[i] / D;

    float* out = (float*)d_out;

    ntn_prep<<<K, D>>>(x2, V, W, b);

    const int smem_bytes = 8448 + STAGES * ROWS_TILE * XSTR * (int)sizeof(float2); // 63744
    cudaFuncSetAttribute(ntn_main, cudaFuncAttributeMaxDynamicSharedMemorySize, smem_bytes);
    const int blocks = (n + ROWS_TILE - 1) / ROWS_TILE;
    ntn_main<<<blocks, TPB, smem_bytes>>>(x1, U, out, n);
}

// round 3
// speedup vs baseline: 2.2398x; 1.0483x over previous
#include <cuda_runtime.h>
#include <stdint.h>

#define D 128
#define K 16
#define TPB 128
#define ROWS_TILE 256          // rows per block (2 per thread)
#define CH 8                   // columns per smem stage
#define NCH (D / CH)           // 16 stages over D
#define XSTR4 3                // float4 per row (2 data + 1 pad) -> 48B stride, conflict-free LDS.128
#define STAGES 3               // cp.async pipeline depth
#define STAGE_BYTES (ROWS_TILE * XSTR4 * 16)   // 12288

// Precomputed A in (cp, k) pair-major layout: gAp[(cp*K + k)] is float2 = (A[k][2cp], A[k][2cp+1])
__device__ __align__(16) float gAp[(D / 2) * K * 2];   // 2048 floats
__device__ float gC[K];

// ---------------- packed f32x2 helpers ----------------
__device__ __forceinline__ void ffma2(unsigned long long& c, unsigned long long a, unsigned long long b) {
    asm("fma.rn.f32x2 %0, %1, %2, %0;" : "+l"(c) : "l"(a), "l"(b));
}
__device__ __forceinline__ void unpack2(float& lo, float& hi, unsigned long long v) {
    asm("mov.b64 {%0, %1}, %2;" : "=f"(lo), "=f"(hi) : "l"(v));
}
__device__ __forceinline__ void cp_async16(uint32_t dst, const void* src, int src_bytes) {
    asm volatile("cp.async.cg.shared.global [%0], [%1], 16, %2;\n"
                 :: "r"(dst), "l"(src), "r"(src_bytes));
}
__device__ __forceinline__ void cp_commit() {
    asm volatile("cp.async.commit_group;\n" ::: "memory");
}
__device__ __forceinline__ void cp_wait2() {
    asm volatile("cp.async.wait_group 2;\n" ::: "memory");
}

// ---------------- prep 1: A rows via warp-per-row dot ----------------
// row = k*D + d ; A[k][d] = V[k][d] + sum_e W[k][d][e] * x2[e]
__global__ void ntn_prep_a(const float* __restrict__ x2,
                           const float* __restrict__ V,
                           const float* __restrict__ W) {
    const int warp = (blockIdx.x * blockDim.x + threadIdx.x) >> 5;
    const int lane = threadIdx.x & 31;
    if (warp >= K * D) return;
    const int k = warp >> 7;
    const int d = warp & (D - 1);

    const float4* wrow = (const float4*)(W + ((size_t)k * D + d) * D);
    const float4* x2v  = (const float4*)x2;
    float dot = 0.f;
    // 128 elems / 32 lanes = 1 float4 per lane
    float4 w4 = wrow[lane];
    float4 x4 = x2v[lane];
    dot = w4.x * x4.x + w4.y * x4.y + w4.z * x4.z + w4.w * x4.w;
#pragma unroll
    for (int s = 16; s > 0; s >>= 1)
        dot += __shfl_xor_sync(0xffffffffu, dot, s);

    if (lane == 0) {
        const float a = V[(size_t)k * 2 * D + d] + dot;
        const int cp = d >> 1, half = d & 1;
        gAp[(cp * K + k) * 2 + half] = a;
    }
}

// ---------------- prep 2: c[k] = V[k, D:] . x2 + b[k] (one warp per k) ----------------
__global__ void ntn_prep_c(const float* __restrict__ x2,
                           const float* __restrict__ V,
                           const float* __restrict__ b) {
    const int k = threadIdx.x >> 5;
    const int lane = threadIdx.x & 31;
    const float4* vrow = (const float4*)(V + (size_t)k * 2 * D + D);
    const float4* x2v  = (const float4*)x2;
    float4 v4 = vrow[lane];
    float4 x4 = x2v[lane];
    float dot = v4.x * x4.x + v4.y * x4.y + v4.z * x4.z + v4.w * x4.w;
#pragma unroll
    for (int s = 16; s > 0; s >>= 1)
        dot += __shfl_xor_sync(0xffffffffu, dot, s);
    if (lane == 0) gC[k] = dot + b[k];
}

// ---------------- main kernel ----------------
__global__ __launch_bounds__(TPB, 4)
void ntn_main(const float* __restrict__ x1,
              const float* __restrict__ U,
              float* __restrict__ out, int n) {
    extern __shared__ __align__(16) char smem_raw[];
    // layout: sA (1024 ull = 8KB) | sC (16f) | sU (16f) | pad to 8448 | xs[STAGES][STAGE_BYTES]
    unsigned long long* sA = (unsigned long long*)smem_raw;
    float* sC = (float*)(smem_raw + 8192);
    float* sU = sC + K;
    char* xs = smem_raw + 8448;
    const uint32_t xs_u32 = (uint32_t)__cvta_generic_to_shared(xs);

    const int tid = threadIdx.x;

    // Load A (1024 x 8B), c, U into smem (covered by first pipeline barrier)
    {
        const unsigned long long* gAu = (const unsigned long long*)gAp;
#pragma unroll
        for (int i = 0; i < 8; i++) sA[tid + i * TPB] = gAu[tid + i * TPB];
        if (tid < K) { sC[tid] = gC[tid]; sU[tid] = U[tid]; }
    }

    const int row0 = blockIdx.x * ROWS_TILE;

    // cp.async issue for one chunk (CH=8 floats = 2 float4 per row) into one stage buffer.
    // 256 rows x 2 float4 = 512 ops / 128 threads = 4 per thread.
    auto issue_chunk = [&](int ch, int buf) {
        const uint32_t base = xs_u32 + (uint32_t)buf * STAGE_BYTES;
#pragma unroll
        for (int it = 0; it < 4; it++) {
            const int idx = it * TPB + tid;
            const int r = idx >> 1;       // 0..255
            const int c = idx & 1;        // float4 within chunk-row
            const int grow = row0 + r;
            const int ok = (grow < n);
            const float* src = x1 + (size_t)(ok ? grow : 0) * D + ch * CH + c * 4;
            cp_async16(base + (uint32_t)(r * XSTR4 + c) * 16u, src, ok ? 16 : 0);
        }
    };

    unsigned long long acc0[K], acc1[K];
#pragma unroll
    for (int k = 0; k < K; k++) { acc0[k] = 0ull; acc1[k] = 0ull; }

    // prologue: stage first STAGES-1 chunks
#pragma unroll
    for (int s = 0; s < STAGES - 1; s++) { issue_chunk(s, s); cp_commit(); }

    for (int ch = 0; ch < NCH; ch++) {
        if (ch + STAGES - 1 < NCH) issue_chunk(ch + STAGES - 1, (ch + STAGES - 1) % STAGES);
        cp_commit();                 // commit every iter (possibly empty) to keep group count aligned
        cp_wait2();                  // <=2 groups pending => chunk ch landed, ch+1/ch+2 in flight
        __syncthreads();

        const int buf = ch % STAGES;
        const ulonglong2* xr0 = (const ulonglong2*)(xs + (size_t)buf * STAGE_BYTES + (size_t)tid * (XSTR4 * 16));
        const ulonglong2* xr1 = (const ulonglong2*)(xs + (size_t)buf * STAGE_BYTES + (size_t)(tid + TPB) * (XSTR4 * 16));

        // 2 float4 per row = 4 packed pairs
        const ulonglong2 qa0 = xr0[0];   // pairs cp 0,1 of this chunk (row a)
        const ulonglong2 qa1 = xr0[1];   // pairs cp 2,3
        const ulonglong2 qb0 = xr1[0];
        const ulonglong2 qb1 = xr1[1];
        const unsigned long long xa[4] = { qa0.x, qa0.y, qa1.x, qa1.y };
        const unsigned long long xb[4] = { qb0.x, qb0.y, qb1.x, qb1.y };

#pragma unroll
        for (int cpl = 0; cpl < 4; cpl++) {
            const int cp = ch * 4 + cpl;
            const ulonglong2* Ab = (const ulonglong2*)(sA + cp * K);
#pragma unroll
            for (int j = 0; j < K / 2; j++) {
                const ulonglong2 a2 = Ab[j];   // broadcast LDS.128: A pairs for k=2j, 2j+1
                ffma2(acc0[2 * j],     xa[cpl], a2.x);
                ffma2(acc0[2 * j + 1], xa[cpl], a2.y);
                ffma2(acc1[2 * j],     xb[cpl], a2.x);
                ffma2(acc1[2 * j + 1], xb[cpl], a2.y);
            }
        }
        __syncthreads();   // protect buf before it is overwritten
    }

    // epilogue: out[r] = sum_k relu(dot_k + c[k]) * U[k]
    float res0 = 0.f, res1 = 0.f;
#pragma unroll
    for (int k = 0; k < K; k++) {
        float lo, hi;
        unpack2(lo, hi, acc0[k]);
        float s0 = lo + hi + sC[k];
        res0 = fmaf(fmaxf(s0, 0.f), sU[k], res0);
        unpack2(lo, hi, acc1[k]);
        float s1 = lo + hi + sC[k];
        res1 = fmaf(fmaxf(s1, 0.f), sU[k], res1);
    }
    const int ra = row0 + tid;
    const int rb = ra + TPB;
    if (ra < n) out[ra] = res0;
    if (rb < n) out[rb] = res1;
}

// ---------------- launch ----------------
extern "C" void kernel_launch(void* const* d_in, const int* in_sizes, int n_in,
                              void* d_out, int out_size) {
    const float* x1 = nullptr; const float* x2 = nullptr; const float* V = nullptr;
    const float* W = nullptr;  const float* b = nullptr;  const float* U = nullptr;
    int n16 = 0;
    for (int i = 0; i < n_in; i++) {
        const int s = in_sizes[i];
        const float* p = (const float*)d_in[i];
        if (s == 128) x2 = p;
        else if (s == 4096) V = p;
        else if (s == 262144) W = p;
        else if (s == 16) { if (n16++ == 0) b = p; else U = p; }
        else x1 = p;
    }
    int n = 0;
    for (int i = 0; i < n_in; i++) if ((const float*)d_in[i] == x1) n = in_sizes[i] / D;

    float* out = (float*)d_out;

    // prep: warp-per-row A (K*D = 2048 warps -> 512 blocks of 128), warp-per-k c
    ntn_prep_a<<<(K * D + 3) / 4, TPB>>>(x2, V, W);
    ntn_prep_c<<<1, K * 32>>>(x2, V, b);

    const int smem_bytes = 8448 + STAGES * STAGE_BYTES;   // 45312
    cudaFuncSetAttribute(ntn_main, cudaFuncAttributeMaxDynamicSharedMemorySize, smem_bytes);
    const int blocks = (n + ROWS_TILE - 1) / ROWS_TILE;
    ntn_main<<<blocks, TPB, smem_bytes>>>(x1, U, out, n);
}

// round 4
// speedup vs baseline: 2.7206x; 1.2147x over previous
#include <cuda_runtime.h>
#include <stdint.h>

#define D 128
#define K 16
#define TPB 128
#define WARPS 4
#define ROWS_TILE 256          // 4 warps x 64 rows
#define CH 16                  // columns per chunk
#define NCH 8                  // chunks per tile (D/CH)
#define ROWSTRIDE 80           // staged row stride in bytes (64 data + 16 pad) -> conflict-free LDS.128
#define STAGE_BYTES (64 * ROWSTRIDE)     // 5120 per stage per warp
#define WARP_STAGING (2 * STAGE_BYTES)   // 2 stages
#define SMEM_HDR 8448                    // A (8192) + c/U (128) + pad
#define SMEM_TOTAL (SMEM_HDR + WARPS * WARP_STAGING)   // 49408
#define NBLK 592               // persistent: 148 SMs x 4 CTAs

// Precomputed A in (cp, k) pair-major: gAp[cp*K + k] is float2 = (A[k][2cp], A[k][2cp+1])
__device__ __align__(16) float gAp[(D / 2) * K * 2];
__device__ float gC[K];

// ---------------- helpers ----------------
__device__ __forceinline__ void ffma2(unsigned long long& c, unsigned long long a, unsigned long long b) {
    asm("fma.rn.f32x2 %0, %1, %2, %0;" : "+l"(c) : "l"(a), "l"(b));
}
__device__ __forceinline__ void unpack2(float& lo, float& hi, unsigned long long v) {
    asm("mov.b64 {%0, %1}, %2;" : "=f"(lo), "=f"(hi) : "l"(v));
}
__device__ __forceinline__ void cp_async16(uint32_t dst, const void* src, int src_bytes) {
    asm volatile("cp.async.cg.shared.global [%0], [%1], 16, %2;\n"
                 :: "r"(dst), "l"(src), "r"(src_bytes));
}
__device__ __forceinline__ void cp_commit() {
    asm volatile("cp.async.commit_group;\n" ::: "memory");
}
__device__ __forceinline__ void cp_wait1() {
    asm volatile("cp.async.wait_group 1;\n" ::: "memory");
}

// ---------------- prep 1: A rows via warp-per-row dot ----------------
__global__ void ntn_prep_a(const float* __restrict__ x2,
                           const float* __restrict__ V,
                           const float* __restrict__ W) {
    const int warp = (blockIdx.x * blockDim.x + threadIdx.x) >> 5;
    const int lane = threadIdx.x & 31;
    if (warp >= K * D) return;
    const int k = warp >> 7;
    const int d = warp & (D - 1);

    const float4* wrow = (const float4*)(W + ((size_t)k * D + d) * D);
    const float4* x2v  = (const float4*)x2;
    float4 w4 = wrow[lane];
    float4 x4 = x2v[lane];
    float dot = w4.x * x4.x + w4.y * x4.y + w4.z * x4.z + w4.w * x4.w;
#pragma unroll
    for (int s = 16; s > 0; s >>= 1)
        dot += __shfl_xor_sync(0xffffffffu, dot, s);

    if (lane == 0) {
        const float a = V[(size_t)k * 2 * D + d] + dot;
        const int cp = d >> 1, half = d & 1;
        gAp[(cp * K + k) * 2 + half] = a;
    }
}

// ---------------- prep 2: c[k] = V[k, D:] . x2 + b[k] ----------------
__global__ void ntn_prep_c(const float* __restrict__ x2,
                           const float* __restrict__ V,
                           const float* __restrict__ b) {
    const int k = threadIdx.x >> 5;
    const int lane = threadIdx.x & 31;
    const float4* vrow = (const float4*)(V + (size_t)k * 2 * D + D);
    const float4* x2v  = (const float4*)x2;
    float4 v4 = vrow[lane];
    float4 x4 = x2v[lane];
    float dot = v4.x * x4.x + v4.y * x4.y + v4.z * x4.z + v4.w * x4.w;
#pragma unroll
    for (int s = 16; s > 0; s >>= 1)
        dot += __shfl_xor_sync(0xffffffffu, dot, s);
    if (lane == 0) gC[k] = dot + b[k];
}

// ---------------- main kernel: persistent, per-warp async pipeline, NO block barriers in loop ----------------
__global__ __launch_bounds__(TPB, 4)
void ntn_main(const float* __restrict__ x1,
              const float* __restrict__ U,
              float* __restrict__ out, int n, int ntiles) {
    extern __shared__ __align__(16) char smem_raw[];
    unsigned long long* sA = (unsigned long long*)smem_raw;     // 1024 ull, cp-major
    float* sC = (float*)(smem_raw + 8192);
    float* sU = sC + K;
    char* staging = smem_raw + SMEM_HDR;

    const int tid = threadIdx.x;
    const int wid = tid >> 5;
    const int lane = tid & 31;

    char* wstage = staging + (size_t)wid * WARP_STAGING;
    const uint32_t wstage_u32 = (uint32_t)__cvta_generic_to_shared(wstage);

    // per-warp chunk issue: 64 rows x 16 cols into stage buf (8 cp.async/lane, 64B/row contig)
    auto issue = [&](int tile, int ch, int buf) {
        const uint32_t base = wstage_u32 + (uint32_t)buf * STAGE_BYTES;
        const int rowbase = tile * ROWS_TILE + wid * 64;
#pragma unroll
        for (int i = 0; i < 8; i++) {
            const int idx = i * 32 + lane;
            const int r = idx >> 2;          // 0..63
            const int c = idx & 3;           // float4 within chunk-row
            const int grow = rowbase + r;
            const int ok = (grow < n);
            const float* src = x1 + (size_t)(ok ? grow : 0) * D + ch * CH + c * 4;
            cp_async16(base + (uint32_t)(r * ROWSTRIDE + c * 16), src, ok ? 16 : 0);
        }
    };

    const int first_tile = blockIdx.x;

    // prologue: kick off the very first chunk before anything else
    if (first_tile < ntiles) { issue(first_tile, 0, 0); cp_commit(); }

    // header: A, c, U (one block barrier total)
    {
        const unsigned long long* gAu = (const unsigned long long*)gAp;
#pragma unroll
        for (int i = 0; i < 8; i++) sA[tid + i * TPB] = gAu[tid + i * TPB];
        if (tid < K) { sC[tid] = gC[tid]; sU[tid] = U[tid]; }
    }
    __syncthreads();

    int g = 0;   // global chunk counter (per warp) -> buffer parity
    for (int tile = first_tile; tile < ntiles; tile += NBLK) {
        unsigned long long acc0[K], acc1[K];
#pragma unroll
        for (int k = 0; k < K; k++) { acc0[k] = 0ull; acc1[k] = 0ull; }

        for (int ch = 0; ch < NCH; ch++) {
            // issue next chunk in the stream (next ch, or chunk 0 of next tile)
            const int nt = (ch == NCH - 1) ? tile + NBLK : tile;
            const int nc = (ch + 1) & (NCH - 1);
            if (nt < ntiles) issue(nt, nc, (g + 1) & 1);
            cp_commit();                    // commit every iter (empty ok) -> uniform group counting
            cp_wait1();                     // <=1 pending => chunk g landed
            __syncwarp();                   // make other lanes' cp.async data visible

            const char* wb = wstage + (size_t)(g & 1) * STAGE_BYTES;
#pragma unroll
            for (int j = 0; j < 4; j++) {
                const ulonglong2 xa = *(const ulonglong2*)(wb + (size_t)lane * ROWSTRIDE + j * 16);
                const ulonglong2 xb = *(const ulonglong2*)(wb + (size_t)(lane + 32) * ROWSTRIDE + j * 16);
#pragma unroll
                for (int h = 0; h < 2; h++) {
                    const int cp = ch * 8 + 2 * j + h;
                    const ulonglong2* Ab = (const ulonglong2*)(sA + cp * K);
                    const unsigned long long xav = h ? xa.y : xa.x;
                    const unsigned long long xbv = h ? xb.y : xb.x;
#pragma unroll
                    for (int k2 = 0; k2 < K / 2; k2++) {
                        const ulonglong2 a2 = Ab[k2];       // broadcast LDS.128
                        ffma2(acc0[2 * k2],     xav, a2.x);
                        ffma2(acc0[2 * k2 + 1], xav, a2.y);
                        ffma2(acc1[2 * k2],     xbv, a2.x);
                        ffma2(acc1[2 * k2 + 1], xbv, a2.y);
                    }
                }
            }
            __syncwarp();   // all lanes done with this buf before it is re-issued
            g++;
        }

        // epilogue (overlaps next tile's chunk-0 DMA)
        float res0 = 0.f, res1 = 0.f;
#pragma unroll
        for (int k = 0; k < K; k++) {
            float lo, hi;
            unpack2(lo, hi, acc0[k]);
            const float s0 = lo + hi + sC[k];
            res0 = fmaf(fmaxf(s0, 0.f), sU[k], res0);
            unpack2(lo, hi, acc1[k]);
            const float s1 = lo + hi + sC[k];
            res1 = fmaf(fmaxf(s1, 0.f), sU[k], res1);
        }
        const int ra = tile * ROWS_TILE + wid * 64 + lane;
        const int rb = ra + 32;
        if (ra < n) out[ra] = res0;
        if (rb < n) out[rb] = res1;
    }
}

// ---------------- launch ----------------
extern "C" void kernel_launch(void* const* d_in, const int* in_sizes, int n_in,
                              void* d_out, int out_size) {
    const float* x1 = nullptr; const float* x2 = nullptr; const float* V = nullptr;
    const float* W = nullptr;  const float* b = nullptr;  const float* U = nullptr;
    int n16 = 0;
    for (int i = 0; i < n_in; i++) {
        const int s = in_sizes[i];
        const float* p = (const float*)d_in[i];
        if (s == 128) x2 = p;
        else if (s == 4096) V = p;
        else if (s == 262144) W = p;
        else if (s == 16) { if (n16++ == 0) b = p; else U = p; }
        else x1 = p;
    }
    int n = 0;
    for (int i = 0; i < n_in; i++) if ((const float*)d_in[i] == x1) n = in_sizes[i] / D;

    float* out = (float*)d_out;

    ntn_prep_a<<<(K * D + 3) / 4, TPB>>>(x2, V, W);
    ntn_prep_c<<<1, K * 32>>>(x2, V, b);

    const int ntiles = (n + ROWS_TILE - 1) / ROWS_TILE;
    const int blocks = ntiles < NBLK ? ntiles : NBLK;
    cudaFuncSetAttribute(ntn_main, cudaFuncAttributeMaxDynamicSharedMemorySize, SMEM_TOTAL);
    ntn_main<<<blocks, TPB, SMEM_TOTAL>>>(x1, U, out, n, ntiles);
}